// round 1
// baseline (speedup 1.0000x reference)
#include <cuda_runtime.h>
#include <math.h>

#define S_LEN  2048
#define NHEAD  16
#define DHEAD  64
#define BATCH  2
#define DMODEL 1024
#define BH     (BATCH*NHEAD)   // 32
#define NPOS   1024            // 2*MAX_REL

// ---------------- static scratch (no runtime allocation allowed) ----------------
__device__ float g_q  [(size_t)BH*S_LEN*DHEAD];        // [b,h,s,d]  16 MB
__device__ float g_k  [(size_t)BH*S_LEN*DHEAD];
__device__ float g_v  [(size_t)BH*S_LEN*DHEAD];
__device__ float g_c2p[BH*NPOS];                       // c2p lookup table
__device__ float g_p2c[(size_t)BH*NPOS*S_LEN];         // [bh][u][j]  268 MB
__device__ float g_ao [(size_t)BATCH*S_LEN*DMODEL];    // attention out, [b,s,h*64+d]

// ---------------- generic C = A @ B^T (+bias) GEMM ----------------
// A: [M,K] row-major, B: [N,K] row-major. 64x64 tile, BK=16, 256 thr, 4x4/thread.
// qkv==1: scatter output to [b,h,s,d] layout (b=m/2048, s=m%2048, h=n/64, d=n%64).
__global__ void __launch_bounds__(256) gemm_nt(
    const float* __restrict__ A, long long sA,
    const float* __restrict__ B, long long sB,
    float* __restrict__ C, long long sC,
    const float* __restrict__ bias,
    int M, int N, int K, int qkv)
{
    A += (long long)blockIdx.z * sA;
    B += (long long)blockIdx.z * sB;
    C += (long long)blockIdx.z * sC;

    __shared__ float As[16][68];   // [k][m]
    __shared__ float Bs[16][68];   // [k][n]

    const int tid = threadIdx.x;
    const int m0 = blockIdx.y << 6, n0 = blockIdx.x << 6;
    const int ty = tid >> 4, tx = tid & 15;
    const int lr = tid >> 2;            // 0..63
    const int lk = (tid & 3) << 2;      // 0,4,8,12

    float acc[4][4] = {};

    for (int k0 = 0; k0 < K; k0 += 16) {
        float4 a4 = *(const float4*)(A + (long long)(m0 + lr)*K + k0 + lk);
        float4 b4 = *(const float4*)(B + (long long)(n0 + lr)*K + k0 + lk);
        As[lk+0][lr] = a4.x; As[lk+1][lr] = a4.y; As[lk+2][lr] = a4.z; As[lk+3][lr] = a4.w;
        Bs[lk+0][lr] = b4.x; Bs[lk+1][lr] = b4.y; Bs[lk+2][lr] = b4.z; Bs[lk+3][lr] = b4.w;
        __syncthreads();
        #pragma unroll
        for (int kk = 0; kk < 16; kk++) {
            float4 av = *(const float4*)&As[kk][ty << 2];
            float4 bv = *(const float4*)&Bs[kk][tx << 2];
            float a[4] = {av.x, av.y, av.z, av.w};
            float b[4] = {bv.x, bv.y, bv.z, bv.w};
            #pragma unroll
            for (int i = 0; i < 4; i++)
                #pragma unroll
                for (int j = 0; j < 4; j++)
                    acc[i][j] += a[i] * b[j];
        }
        __syncthreads();
    }

    float4 bb4 = make_float4(0.f, 0.f, 0.f, 0.f);
    if (bias) bb4 = *(const float4*)(bias + n0 + (tx << 2));
    const float bb[4] = {bb4.x, bb4.y, bb4.z, bb4.w};

    #pragma unroll
    for (int i = 0; i < 4; i++) {
        int m = m0 + (ty << 2) + i;
        float4 o4 = make_float4(acc[i][0] + bb[0], acc[i][1] + bb[1],
                                acc[i][2] + bb[2], acc[i][3] + bb[3]);
        if (qkv) {
            int b = m >> 11;          // / 2048
            int s = m & 2047;
            int h = n0 >> 6;          // tile spans exactly one head
            long long off = ((((long long)b*NHEAD + h)*S_LEN + s) << 6) + (tx << 2);
            *(float4*)(C + off) = o4;
        } else {
            *(float4*)(C + (long long)m*N + n0 + (tx << 2)) = o4;
        }
    }
}

// ---------------- qsum + c2p table: c2p[bh][u] = (sum_s q[bh,s,:]) . PT[u,:] ----------------
__global__ void __launch_bounds__(256) c2p_kernel(const float* __restrict__ pt)
{
    const int bh = blockIdx.x;
    const float* q = g_q + (long long)bh*S_LEN*DHEAD;
    __shared__ float part[256];
    __shared__ float qsum[64];
    const int tid = threadIdx.x;
    const int d = tid & 63, sg = tid >> 6;

    float acc = 0.f;
    for (int s = sg; s < S_LEN; s += 4) acc += q[s*64 + d];
    part[tid] = acc;
    __syncthreads();
    if (tid < 64) qsum[tid] = part[tid] + part[tid+64] + part[tid+128] + part[tid+192];
    __syncthreads();

    for (int u = tid; u < NPOS; u += 256) {
        float vsum = 0.f;
        #pragma unroll 16
        for (int dd = 0; dd < 64; dd++) vsum += qsum[dd] * pt[u*64 + dd];
        g_c2p[bh*NPOS + u] = vsum;
    }
}

// ---------------- flash attention with disentangled bias ----------------
// grid: (S/64 i-tiles, BH). 256 threads; thread (ty,tx) owns rows ty*4..+3, cols tx*4..+3.
#define FLASH_SMEM_FLOATS (4*64*68 + 127*66 + 1024)

__global__ void __launch_bounds__(256) flash_attn()
{
    const int bh = blockIdx.y;
    const int i0 = blockIdx.x << 6;
    const float* q   = g_q + (long long)bh*S_LEN*DHEAD;
    const float* k   = g_k + (long long)bh*S_LEN*DHEAD;
    const float* v   = g_v + (long long)bh*S_LEN*DHEAD;
    const float* c2p = g_c2p + bh*NPOS;
    const float* p2c = g_p2c + (long long)bh*NPOS*S_LEN;

    extern __shared__ float sm[];
    float* qs   = sm;                 // [64][68]  [d][r], pre-scaled by 1/8
    float* ks   = qs + 64*68;         // [64][68]  [d][c]
    float* vs   = ks + 64*68;         // [64][68]  [c][d]
    float* ps   = vs + 64*68;         // [64][68]  [c][r]  (transposed P)
    float* stg  = ps + 64*68;         // [127][66] p2c band staging
    float* c2ps = stg + 127*66;       // [1024]

    const int tid = threadIdx.x;
    const int ty = tid >> 4, tx = tid & 15;

    // load Q tile transposed + pre-scaled
    for (int idx = tid; idx < 4096; idx += 256) {
        int r = idx >> 6, d = idx & 63;
        qs[d*68 + r] = q[(i0 + r)*64 + d] * 0.125f;
    }
    for (int u = tid; u < NPOS; u += 256) c2ps[u] = c2p[u];

    float o[4][4] = {};
    float mrow[4] = {-1e30f, -1e30f, -1e30f, -1e30f};
    float lrow[4] = {};

    for (int j0 = 0; j0 < S_LEN; j0 += 64) {
        __syncthreads();   // previous PV done (and first-iter q/c2p loads visible)

        // load K (transposed) and V tiles
        for (int idx = tid; idx < 4096; idx += 256) {
            int c = idx >> 6, d = idx & 63;
            ks[d*68 + c] = k[(j0 + c)*64 + d];
            vs[c*68 + d] = v[(j0 + c)*64 + d];
        }
        // stage p2c band: u_raw = 2559 - r - c spans [u_lo, u_lo+126]; clamp at load
        const int u_lo = 2433 - i0 - j0;
        for (int idx = tid; idx < 127*64; idx += 256) {
            int su = idx >> 6, cc = idx & 63;
            int u = u_lo + su;
            u = min(max(u, 0), NPOS - 1);
            stg[su*66 + cc] = p2c[(long long)u*S_LEN + j0 + cc];
        }
        __syncthreads();

        // scores: S = (q*scale) @ k^T
        float s[4][4] = {};
        #pragma unroll 8
        for (int d = 0; d < 64; d++) {
            float4 qv = *(const float4*)&qs[d*68 + (ty << 2)];
            float4 kv = *(const float4*)&ks[d*68 + (tx << 2)];
            float a[4] = {qv.x, qv.y, qv.z, qv.w};
            float b[4] = {kv.x, kv.y, kv.z, kv.w};
            #pragma unroll
            for (int i = 0; i < 4; i++)
                #pragma unroll
                for (int j = 0; j < 4; j++)
                    s[i][j] += a[i] * b[j];
        }

        // add bias = c2p lookup + p2c gather
        #pragma unroll
        for (int i = 0; i < 4; i++) {
            int r = i0 + (ty << 2) + i;
            #pragma unroll
            for (int j = 0; j < 4; j++) {
                int c = j0 + (tx << 2) + j;
                int ic = r - c + 512;
                ic = min(max(ic, 0), NPOS - 1);
                int su = (2559 - r - c) - u_lo;     // in [0,126]
                s[i][j] += c2ps[ic] + stg[su*66 + ((tx << 2) + j)];
            }
        }

        // online softmax per row (4 lanes... 16 tx lanes share a row -> width-16 shfl)
        #pragma unroll
        for (int i = 0; i < 4; i++) {
            float rm = fmaxf(fmaxf(s[i][0], s[i][1]), fmaxf(s[i][2], s[i][3]));
            rm = fmaxf(rm, __shfl_xor_sync(0xffffffffu, rm, 1, 16));
            rm = fmaxf(rm, __shfl_xor_sync(0xffffffffu, rm, 2, 16));
            rm = fmaxf(rm, __shfl_xor_sync(0xffffffffu, rm, 4, 16));
            rm = fmaxf(rm, __shfl_xor_sync(0xffffffffu, rm, 8, 16));
            float mn  = fmaxf(mrow[i], rm);
            float fac = __expf(mrow[i] - mn);
            mrow[i] = mn;
            float rs = 0.f;
            #pragma unroll
            for (int j = 0; j < 4; j++) { s[i][j] = __expf(s[i][j] - mn); rs += s[i][j]; }
            rs += __shfl_xor_sync(0xffffffffu, rs, 1, 16);
            rs += __shfl_xor_sync(0xffffffffu, rs, 2, 16);
            rs += __shfl_xor_sync(0xffffffffu, rs, 4, 16);
            rs += __shfl_xor_sync(0xffffffffu, rs, 8, 16);
            lrow[i] = lrow[i]*fac + rs;
            #pragma unroll
            for (int j = 0; j < 4; j++) o[i][j] *= fac;
        }

        // write P transposed for PV pass
        #pragma unroll
        for (int i = 0; i < 4; i++)
            #pragma unroll
            for (int j = 0; j < 4; j++)
                ps[((tx << 2) + j)*68 + (ty << 2) + i] = s[i][j];
        __syncthreads();

        // O += P @ V
        #pragma unroll 8
        for (int c = 0; c < 64; c++) {
            float4 pv = *(const float4*)&ps[c*68 + (ty << 2)];
            float4 vv = *(const float4*)&vs[c*68 + (tx << 2)];
            float a[4] = {pv.x, pv.y, pv.z, pv.w};
            float b[4] = {vv.x, vv.y, vv.z, vv.w};
            #pragma unroll
            for (int i = 0; i < 4; i++)
                #pragma unroll
                for (int j = 0; j < 4; j++)
                    o[i][j] += a[i] * b[j];
        }
    }

    // epilogue: normalize, store as [b, s, h*64+d]
    const int b = bh >> 4, h = bh & 15;
    #pragma unroll
    for (int i = 0; i < 4; i++) {
        int r = i0 + (ty << 2) + i;
        float inv = 1.0f / lrow[i];
        float4 o4 = make_float4(o[i][0]*inv, o[i][1]*inv, o[i][2]*inv, o[i][3]*inv);
        long long off = ((long long)b*S_LEN + r)*DMODEL + h*DHEAD + (tx << 2);
        *(float4*)(g_ao + off) = o4;
    }
}

// ---------------- launch ----------------
extern "C" void kernel_launch(void* const* d_in, const int* in_sizes, int n_in,
                              void* d_out, int out_size)
{
    const float* hidden = (const float*)d_in[0];
    const float* Wq = (const float*)d_in[1];
    const float* bq = (const float*)d_in[2];
    const float* Wk = (const float*)d_in[3];
    const float* bk = (const float*)d_in[4];
    const float* Wv = (const float*)d_in[5];
    const float* bv = (const float*)d_in[6];
    const float* Wc = (const float*)d_in[7];
    const float* pt = (const float*)d_in[8];
    float* out = (float*)d_out;

    float *pq, *pk, *pv, *pp2c, *pao;
    cudaGetSymbolAddress((void**)&pq,   g_q);
    cudaGetSymbolAddress((void**)&pk,   g_k);
    cudaGetSymbolAddress((void**)&pv,   g_v);
    cudaGetSymbolAddress((void**)&pp2c, g_p2c);
    cudaGetSymbolAddress((void**)&pao,  g_ao);

    const int flash_smem = FLASH_SMEM_FLOATS * (int)sizeof(float);
    cudaFuncSetAttribute(flash_attn, cudaFuncAttributeMaxDynamicSharedMemorySize, flash_smem);

    dim3 blk(256);
    const int M = BATCH * S_LEN;   // 4096

    // QKV projections: C = hidden @ W^T + b, scattered to [b,h,s,d]
    gemm_nt<<<dim3(DMODEL/64, M/64, 1), blk>>>(hidden, 0, Wq, 0, pq, 0, bq, M, DMODEL, DMODEL, 1);
    gemm_nt<<<dim3(DMODEL/64, M/64, 1), blk>>>(hidden, 0, Wk, 0, pk, 0, bk, M, DMODEL, DMODEL, 1);
    gemm_nt<<<dim3(DMODEL/64, M/64, 1), blk>>>(hidden, 0, Wv, 0, pv, 0, bv, M, DMODEL, DMODEL, 1);

    // c2p lookup table per (b,h)
    c2p_kernel<<<BH, 256>>>(pt);

    // P2C[bh][u][j] = PT[u,:] . k[bh,j,:]   (batched GEMM, K=64)
    gemm_nt<<<dim3(S_LEN/64, NPOS/64, BH), blk>>>(
        pt, 0, pk, (long long)S_LEN*DHEAD, pp2c, (long long)NPOS*S_LEN,
        nullptr, NPOS, S_LEN, DHEAD, 0);

    // fused attention
    flash_attn<<<dim3(S_LEN/64, BH), blk, flash_smem>>>();

    // c_proj: out = attn_out @ Wc^T
    gemm_nt<<<dim3(DMODEL/64, M/64, 1), blk>>>(pao, 0, Wc, 0, out, 0, nullptr, M, DMODEL, DMODEL, 0);
}

// round 2
// speedup vs baseline: 1.0277x; 1.0277x over previous
#include <cuda_runtime.h>
#include <math.h>

#define S_LEN  2048
#define NHEAD  16
#define DHEAD  64
#define BATCH  2
#define DMODEL 1024
#define BH     (BATCH*NHEAD)   // 32
#define NPOS   1024            // 2*MAX_REL

typedef unsigned long long ull;

// ---------------- static scratch ----------------
__device__ float g_q  [(size_t)BH*S_LEN*DHEAD];
__device__ float g_k  [(size_t)BH*S_LEN*DHEAD];
__device__ float g_v  [(size_t)BH*S_LEN*DHEAD];
__device__ float g_c2p[BH*NPOS];
__device__ float g_p2c[(size_t)BH*NPOS*S_LEN];         // [bh][u][j]
__device__ float g_ao [(size_t)BATCH*S_LEN*DMODEL];    // [b,s,h*64+d]

// ---------------- f32x2 helpers (FFMA2 path) ----------------
__device__ __forceinline__ void ffma2(ull& d, ull a, ull b) {
    asm("fma.rn.f32x2 %0, %1, %2, %0;" : "+l"(d) : "l"(a), "l"(b));
}
__device__ __forceinline__ void fmul2(ull& d, ull a, ull b) {
    asm("mul.rn.f32x2 %0, %1, %2;" : "=l"(d) : "l"(a), "l"(b));
}
__device__ __forceinline__ ull pack2(float lo, float hi) {
    ull r;
    asm("mov.b64 %0, {%1, %2};" : "=l"(r) : "r"(__float_as_uint(lo)), "r"(__float_as_uint(hi)));
    return r;
}
__device__ __forceinline__ float2 unpack2(ull v) {
    unsigned int lo, hi;
    asm("mov.b64 {%0, %1}, %2;" : "=r"(lo), "=r"(hi) : "l"(v));
    return make_float2(__uint_as_float(lo), __uint_as_float(hi));
}

// ---------------- shared GEMM mainloop: 128x128 tile, BK=16, 256 thr, 8x8 micro ----------------
#define LDSS 132
// smem: 4 buffers of 16*LDSS floats: A0 B0 A1 B1
__device__ __forceinline__ void gemm_mainloop(
    const float* __restrict__ A, int lda,
    const float* __restrict__ B, int ldb,
    int K, float* sm, ull acc[4][8])
{
    const int tid = threadIdx.x;
    const int row = tid >> 1;
    const int kc  = (tid & 1) << 3;
    const int ty8 = (tid >> 4) << 3;
    const int tx8 = (tid & 15) << 3;

    float* bufA[2] = { sm,              sm + 2*16*LDSS };
    float* bufB[2] = { sm + 16*LDSS,    sm + 3*16*LDSS };

    const float* pa = A + (size_t)row*lda + kc;
    const float* pb = B + (size_t)row*ldb + kc;

    float4 a0 = *(const float4*)(pa);
    float4 a1 = *(const float4*)(pa + 4);
    float4 b0 = *(const float4*)(pb);
    float4 b1 = *(const float4*)(pb + 4);
    {
        float* As = bufA[0]; float* Bs = bufB[0];
        As[(kc+0)*LDSS+row]=a0.x; As[(kc+1)*LDSS+row]=a0.y; As[(kc+2)*LDSS+row]=a0.z; As[(kc+3)*LDSS+row]=a0.w;
        As[(kc+4)*LDSS+row]=a1.x; As[(kc+5)*LDSS+row]=a1.y; As[(kc+6)*LDSS+row]=a1.z; As[(kc+7)*LDSS+row]=a1.w;
        Bs[(kc+0)*LDSS+row]=b0.x; Bs[(kc+1)*LDSS+row]=b0.y; Bs[(kc+2)*LDSS+row]=b0.z; Bs[(kc+3)*LDSS+row]=b0.w;
        Bs[(kc+4)*LDSS+row]=b1.x; Bs[(kc+5)*LDSS+row]=b1.y; Bs[(kc+6)*LDSS+row]=b1.z; Bs[(kc+7)*LDSS+row]=b1.w;
    }
    __syncthreads();

    const int nst = K >> 4;
    int p = 0;
    for (int s = 0; s < nst; s++) {
        if (s + 1 < nst) {
            const float* qa = pa + ((s+1) << 4);
            const float* qb = pb + ((s+1) << 4);
            a0 = *(const float4*)(qa); a1 = *(const float4*)(qa + 4);
            b0 = *(const float4*)(qb); b1 = *(const float4*)(qb + 4);
        }
        const float* As = bufA[p]; const float* Bs = bufB[p];
        #pragma unroll
        for (int kk = 0; kk < 16; kk++) {
            ulonglong2 ra = *(const ulonglong2*)&As[kk*LDSS + ty8];
            ulonglong2 rb = *(const ulonglong2*)&As[kk*LDSS + ty8 + 4];
            float4 c0 = *(const float4*)&Bs[kk*LDSS + tx8];
            float4 c1 = *(const float4*)&Bs[kk*LDSS + tx8 + 4];
            ull ar[4] = { ra.x, ra.y, rb.x, rb.y };
            ull bb[8] = { pack2(c0.x,c0.x), pack2(c0.y,c0.y), pack2(c0.z,c0.z), pack2(c0.w,c0.w),
                          pack2(c1.x,c1.x), pack2(c1.y,c1.y), pack2(c1.z,c1.z), pack2(c1.w,c1.w) };
            #pragma unroll
            for (int i = 0; i < 4; i++)
                #pragma unroll
                for (int j = 0; j < 8; j++)
                    ffma2(acc[i][j], ar[i], bb[j]);
        }
        __syncthreads();
        if (s + 1 < nst) {
            int q = p ^ 1;
            float* As = bufA[q]; float* Bs = bufB[q];
            As[(kc+0)*LDSS+row]=a0.x; As[(kc+1)*LDSS+row]=a0.y; As[(kc+2)*LDSS+row]=a0.z; As[(kc+3)*LDSS+row]=a0.w;
            As[(kc+4)*LDSS+row]=a1.x; As[(kc+5)*LDSS+row]=a1.y; As[(kc+6)*LDSS+row]=a1.z; As[(kc+7)*LDSS+row]=a1.w;
            Bs[(kc+0)*LDSS+row]=b0.x; Bs[(kc+1)*LDSS+row]=b0.y; Bs[(kc+2)*LDSS+row]=b0.z; Bs[(kc+3)*LDSS+row]=b0.w;
            Bs[(kc+4)*LDSS+row]=b1.x; Bs[(kc+5)*LDSS+row]=b1.y; Bs[(kc+6)*LDSS+row]=b1.z; Bs[(kc+7)*LDSS+row]=b1.w;
            __syncthreads();
            p = q;
        }
    }
}

// ---------------- fused QKV GEMM, scatter to [b,h,s,d] ----------------
__global__ void __launch_bounds__(256) qkv_gemm(
    const float* __restrict__ X,
    const float* __restrict__ Wq, const float* __restrict__ Wk, const float* __restrict__ Wv,
    const float* __restrict__ bq, const float* __restrict__ bk, const float* __restrict__ bv)
{
    __shared__ float sm[4*16*LDSS];
    const int n_glob = blockIdx.x << 7;      // 0..2944
    const int m0     = blockIdx.y << 7;
    const int w      = n_glob >> 10;
    const int n_in   = n_glob & 1023;

    const float* Bw; const float* bw; float* Cw;
    if      (w == 0) { Bw = Wq; bw = bq; Cw = g_q; }
    else if (w == 1) { Bw = Wk; bw = bk; Cw = g_k; }
    else             { Bw = Wv; bw = bv; Cw = g_v; }

    ull acc[4][8] = {};
    gemm_mainloop(X + (size_t)m0*DMODEL, DMODEL, Bw + (size_t)n_in*DMODEL, DMODEL, DMODEL, sm, acc);

    const int tid = threadIdx.x;
    const int ty8 = (tid >> 4) << 3;
    const int tx8 = (tid & 15) << 3;

    float4 bA = *(const float4*)&bw[n_in + tx8];
    float4 bB = *(const float4*)&bw[n_in + tx8 + 4];
    const float bb[8] = { bA.x, bA.y, bA.z, bA.w, bB.x, bB.y, bB.z, bB.w };

    float ov[8][8];
    #pragma unroll
    for (int i2 = 0; i2 < 4; i2++)
        #pragma unroll
        for (int j = 0; j < 8; j++) {
            float2 t = unpack2(acc[i2][j]);
            ov[2*i2][j]   = t.x + bb[j];
            ov[2*i2+1][j] = t.y + bb[j];
        }

    const int ng = n_in + tx8;
    const int h  = ng >> 6;
    const int d0 = ng & 63;
    #pragma unroll
    for (int rr = 0; rr < 8; rr++) {
        int m = m0 + ty8 + rr;
        int b = m >> 11, s = m & 2047;
        float* dst = Cw + ((((size_t)b*NHEAD + h)*S_LEN + s) << 6) + d0;
        *(float4*)(dst)     = make_float4(ov[rr][0], ov[rr][1], ov[rr][2], ov[rr][3]);
        *(float4*)(dst + 4) = make_float4(ov[rr][4], ov[rr][5], ov[rr][6], ov[rr][7]);
    }
}

// ---------------- generic plain GEMM C = A @ B^T (batched) ----------------
__global__ void __launch_bounds__(256) gemm128(
    const float* __restrict__ A, int lda, long long sA,
    const float* __restrict__ B, int ldb, long long sB,
    float* __restrict__ C, int ldc, long long sC, int K)
{
    __shared__ float sm[4*16*LDSS];
    A += (long long)blockIdx.z * sA;
    B += (long long)blockIdx.z * sB;
    C += (long long)blockIdx.z * sC;
    const int n0 = blockIdx.x << 7;
    const int m0 = blockIdx.y << 7;

    ull acc[4][8] = {};
    gemm_mainloop(A + (size_t)m0*lda, lda, B + (size_t)n0*ldb, ldb, K, sm, acc);

    const int tid = threadIdx.x;
    const int ty8 = (tid >> 4) << 3;
    const int tx8 = (tid & 15) << 3;

    #pragma unroll
    for (int i2 = 0; i2 < 4; i2++) {
        float r0[8], r1[8];
        #pragma unroll
        for (int j = 0; j < 8; j++) {
            float2 t = unpack2(acc[i2][j]);
            r0[j] = t.x; r1[j] = t.y;
        }
        float* d0 = C + (size_t)(m0 + ty8 + 2*i2)*ldc + n0 + tx8;
        float* d1 = d0 + ldc;
        *(float4*)(d0)   = make_float4(r0[0], r0[1], r0[2], r0[3]);
        *(float4*)(d0+4) = make_float4(r0[4], r0[5], r0[6], r0[7]);
        *(float4*)(d1)   = make_float4(r1[0], r1[1], r1[2], r1[3]);
        *(float4*)(d1+4) = make_float4(r1[4], r1[5], r1[6], r1[7]);
    }
}

// ---------------- c2p table: c2p[bh][u] = (sum_s q[bh,s,:]) . PT[u,:] ----------------
__global__ void __launch_bounds__(256) c2p_kernel(const float* __restrict__ pt)
{
    const int bh = blockIdx.x;
    const float* q = g_q + (size_t)bh*S_LEN*DHEAD;
    __shared__ float part[256];
    __shared__ float qsum[64];
    const int tid = threadIdx.x;
    const int d = tid & 63, sg = tid >> 6;

    float acc = 0.f;
    for (int s = sg; s < S_LEN; s += 4) acc += q[s*64 + d];
    part[tid] = acc;
    __syncthreads();
    if (tid < 64) qsum[tid] = part[tid] + part[tid+64] + part[tid+128] + part[tid+192];
    __syncthreads();

    const int u = (blockIdx.y << 8) + tid;
    float vsum = 0.f;
    #pragma unroll 16
    for (int dd = 0; dd < 64; dd++) vsum += qsum[dd] * pt[u*64 + dd];
    g_c2p[bh*NPOS + u] = vsum;
}

// ---------------- flash attention: 128(i) x 64(j) tiles, 8x4 micro, FFMA2 ----------------
#define FLASH_SMEM_FLOATS (64*132 + 64*68 + 64*68 + 64*132 + 191*68 + 1024)

__global__ void __launch_bounds__(256) flash_attn()
{
    const int bh = blockIdx.y;
    const int i0 = blockIdx.x << 7;
    const float* q   = g_q + (size_t)bh*S_LEN*DHEAD;
    const float* k   = g_k + (size_t)bh*S_LEN*DHEAD;
    const float* v   = g_v + (size_t)bh*S_LEN*DHEAD;
    const float* c2p = g_c2p + bh*NPOS;
    const float* p2c = g_p2c + (size_t)bh*NPOS*S_LEN;

    extern __shared__ float smf[];
    float* qs   = smf;                 // [64][132]  [d][r], pre-scaled
    float* ks   = qs + 64*132;         // [64][68]   [d][c]
    float* vs   = ks + 64*68;          // [64][68]   [c][d]
    float* ps   = vs + 64*68;          // [64][132]  [c][r]
    float* stg  = ps + 64*132;         // [191][68]
    float* c2ps = stg + 191*68;        // [1024]

    const int tid = threadIdx.x;
    const int ty8 = (tid >> 4) << 3;   // row base 0..120
    const int tx4 = (tid & 15) << 2;   // col base 0..60

    // load Q tile transposed + pre-scaled (1/sqrt(64))
    for (int idx = tid; idx < 128*64; idx += 256) {
        int r = idx >> 6, d = idx & 63;
        qs[d*132 + r] = q[(i0 + r)*64 + d] * 0.125f;
    }
    for (int u = tid; u < NPOS; u += 256) c2ps[u] = c2p[u];

    ull o2[4][4] = {};
    float mrow[8], lrow[8];
    #pragma unroll
    for (int i = 0; i < 8; i++) { mrow[i] = -1e30f; lrow[i] = 0.f; }

    for (int j0 = 0; j0 < S_LEN; j0 += 64) {
        __syncthreads();

        // load K transposed [d][c] and V [c][d]
        for (int idx = tid; idx < 1024; idx += 256) {
            int c = idx >> 4, d4 = (idx & 15) << 2;
            float4 t = *(const float4*)&k[(j0 + c)*64 + d4];
            ks[(d4+0)*68 + c] = t.x; ks[(d4+1)*68 + c] = t.y;
            ks[(d4+2)*68 + c] = t.z; ks[(d4+3)*68 + c] = t.w;
            *(float4*)&vs[c*68 + d4] = *(const float4*)&v[(j0 + c)*64 + d4];
        }
        // stage p2c band: u = 2559 - r - c, su = 190 - rl - cl
        const int u_lo = 2369 - i0 - j0;
        for (int idx = tid; idx < 191*16; idx += 256) {
            int su = idx >> 4, c4 = (idx & 15) << 2;
            int u = min(max(u_lo + su, 0), NPOS - 1);
            *(float4*)&stg[su*68 + c4] = *(const float4*)&p2c[(size_t)u*S_LEN + j0 + c4];
        }
        __syncthreads();

        // QK^T
        ull s2[4][4] = {};
        #pragma unroll 8
        for (int d = 0; d < 64; d++) {
            ulonglong2 qa = *(const ulonglong2*)&qs[d*132 + ty8];
            ulonglong2 qb = *(const ulonglong2*)&qs[d*132 + ty8 + 4];
            float4 kf = *(const float4*)&ks[d*68 + tx4];
            ull ar[4] = { qa.x, qa.y, qb.x, qb.y };
            ull bv[4] = { pack2(kf.x,kf.x), pack2(kf.y,kf.y), pack2(kf.z,kf.z), pack2(kf.w,kf.w) };
            #pragma unroll
            for (int i = 0; i < 4; i++)
                #pragma unroll
                for (int j = 0; j < 4; j++)
                    ffma2(s2[i][j], ar[i], bv[j]);
        }

        // unpack + bias
        float s[8][4];
        #pragma unroll
        for (int i2 = 0; i2 < 4; i2++)
            #pragma unroll
            for (int j = 0; j < 4; j++) {
                float2 t = unpack2(s2[i2][j]);
                s[2*i2][j] = t.x; s[2*i2+1][j] = t.y;
            }
        #pragma unroll
        for (int rr = 0; rr < 8; rr++) {
            int r = i0 + ty8 + rr;
            #pragma unroll
            for (int j = 0; j < 4; j++) {
                int c = j0 + tx4 + j;
                int ic = min(max(r - c + 512, 0), NPOS - 1);
                int su = 190 - (ty8 + rr) - (tx4 + j);
                s[rr][j] += c2ps[ic] + stg[su*68 + tx4 + j];
            }
        }

        // online softmax (rows shared by 16 tx lanes)
        float fac[8];
        #pragma unroll
        for (int rr = 0; rr < 8; rr++) {
            float rm = fmaxf(fmaxf(s[rr][0], s[rr][1]), fmaxf(s[rr][2], s[rr][3]));
            rm = fmaxf(rm, __shfl_xor_sync(0xffffffffu, rm, 1, 16));
            rm = fmaxf(rm, __shfl_xor_sync(0xffffffffu, rm, 2, 16));
            rm = fmaxf(rm, __shfl_xor_sync(0xffffffffu, rm, 4, 16));
            rm = fmaxf(rm, __shfl_xor_sync(0xffffffffu, rm, 8, 16));
            float mn = fmaxf(mrow[rr], rm);
            fac[rr] = __expf(mrow[rr] - mn);
            mrow[rr] = mn;
            float rs = 0.f;
            #pragma unroll
            for (int j = 0; j < 4; j++) { s[rr][j] = __expf(s[rr][j] - mn); rs += s[rr][j]; }
            rs += __shfl_xor_sync(0xffffffffu, rs, 1, 16);
            rs += __shfl_xor_sync(0xffffffffu, rs, 2, 16);
            rs += __shfl_xor_sync(0xffffffffu, rs, 4, 16);
            rs += __shfl_xor_sync(0xffffffffu, rs, 8, 16);
            lrow[rr] = lrow[rr]*fac[rr] + rs;
        }
        // rescale O pairs
        #pragma unroll
        for (int i2 = 0; i2 < 4; i2++) {
            ull f2 = pack2(fac[2*i2], fac[2*i2+1]);
            #pragma unroll
            for (int j = 0; j < 4; j++) fmul2(o2[i2][j], o2[i2][j], f2);
        }

        // write P transposed [c][r] (vectorized: 8 consecutive rows)
        #pragma unroll
        for (int j = 0; j < 4; j++) {
            int c = tx4 + j;
            *(float4*)&ps[c*132 + ty8]     = make_float4(s[0][j], s[1][j], s[2][j], s[3][j]);
            *(float4*)&ps[c*132 + ty8 + 4] = make_float4(s[4][j], s[5][j], s[6][j], s[7][j]);
        }
        __syncthreads();

        // O += P @ V
        #pragma unroll 8
        for (int c = 0; c < 64; c++) {
            ulonglong2 pa = *(const ulonglong2*)&ps[c*132 + ty8];
            ulonglong2 pb = *(const ulonglong2*)&ps[c*132 + ty8 + 4];
            float4 vf = *(const float4*)&vs[c*68 + tx4];
            ull ar[4] = { pa.x, pa.y, pb.x, pb.y };
            ull bv[4] = { pack2(vf.x,vf.x), pack2(vf.y,vf.y), pack2(vf.z,vf.z), pack2(vf.w,vf.w) };
            #pragma unroll
            for (int i = 0; i < 4; i++)
                #pragma unroll
                for (int j = 0; j < 4; j++)
                    ffma2(o2[i][j], ar[i], bv[j]);
        }
    }

    // epilogue
    const int b = bh >> 4, h = bh & 15;
    float o[8][4];
    #pragma unroll
    for (int i2 = 0; i2 < 4; i2++)
        #pragma unroll
        for (int j = 0; j < 4; j++) {
            float2 t = unpack2(o2[i2][j]);
            o[2*i2][j] = t.x; o[2*i2+1][j] = t.y;
        }
    #pragma unroll
    for (int rr = 0; rr < 8; rr++) {
        float inv = 1.0f / lrow[rr];
        int r = i0 + ty8 + rr;
        float4 o4 = make_float4(o[rr][0]*inv, o[rr][1]*inv, o[rr][2]*inv, o[rr][3]*inv);
        *(float4*)(g_ao + ((size_t)b*S_LEN + r)*DMODEL + h*DHEAD + tx4) = o4;
    }
}

// ---------------- launch ----------------
extern "C" void kernel_launch(void* const* d_in, const int* in_sizes, int n_in,
                              void* d_out, int out_size)
{
    const float* hidden = (const float*)d_in[0];
    const float* Wq = (const float*)d_in[1];
    const float* bq = (const float*)d_in[2];
    const float* Wk = (const float*)d_in[3];
    const float* bk = (const float*)d_in[4];
    const float* Wv = (const float*)d_in[5];
    const float* bv = (const float*)d_in[6];
    const float* Wc = (const float*)d_in[7];
    const float* pt = (const float*)d_in[8];
    float* out = (float*)d_out;

    float *pk, *pp2c, *pao;
    cudaGetSymbolAddress((void**)&pk,   g_k);
    cudaGetSymbolAddress((void**)&pp2c, g_p2c);
    cudaGetSymbolAddress((void**)&pao,  g_ao);

    const int flash_smem = FLASH_SMEM_FLOATS * (int)sizeof(float);
    static int once = 0;
    if (!once) {
        cudaFuncSetAttribute(flash_attn, cudaFuncAttributeMaxDynamicSharedMemorySize, flash_smem);
        once = 1;
    }

    // QKV projections (fused), scatter to [b,h,s,d]
    qkv_gemm<<<dim3(24, 32), 256>>>(hidden, Wq, Wk, Wv, bq, bk, bv);

    // c2p lookup table
    c2p_kernel<<<dim3(BH, 4), 256>>>(pt);

    // P2C[bh][u][j] = PT[u,:] . k[bh,j,:]
    gemm128<<<dim3(S_LEN/128, NPOS/128, BH), 256>>>(
        pt, DHEAD, 0, pk, DHEAD, (long long)S_LEN*DHEAD,
        pp2c, S_LEN, (long long)NPOS*S_LEN, DHEAD);

    // fused attention
    flash_attn<<<dim3(S_LEN/128, BH), 256, flash_smem>>>();

    // c_proj
    gemm128<<<dim3(DMODEL/128, (BATCH*S_LEN)/128, 1), 256>>>(
        pao, DMODEL, 0, Wc, DMODEL, 0, out, DMODEL, 0, DMODEL);
}